// round 2
// baseline (speedup 1.0000x reference)
#include <cuda_runtime.h>
#include <math.h>

#define BB 64
#define SS 512
#define CC 1024
#define HH 1024
#define G3 3072   // 3*H

// ---------------- scratch (static device globals; no runtime allocation) ----------------
__device__ float d_g0[(size_t)SS * BB * G3];   // precomputed layer-0 input projections (+b_ih0)
__device__ float d_h0[2][BB * HH];             // double-buffered layer-0 hidden
__device__ float d_h1[2][BB * HH];             // double-buffered layer-1 hidden
__device__ float d_gh1[BB * G3];               // layer-1 recurrent gates buffer, packed (hc*3+g)
__device__ unsigned int d_bar_arrive;
__device__ unsigned int d_bar_gen;

// ---------------- grid-wide barrier (sense-reversing via generation counter) ----------------
__device__ __forceinline__ void grid_sync(int nblocks) {
    __syncthreads();
    if (threadIdx.x == 0) {
        __threadfence();  // publish our writes (also CCTL.IVALL -> L1 invalidate on this arch)
        unsigned int gen = *((volatile unsigned int*)&d_bar_gen);
        if (atomicAdd(&d_bar_arrive, 1u) == (unsigned int)(nblocks - 1)) {
            atomicExch(&d_bar_arrive, 0u);
            __threadfence();
            atomicExch(&d_bar_gen, gen + 1u);
        } else {
            while (*((volatile unsigned int*)&d_bar_gen) == gen) { __nanosleep(64); }
        }
        __threadfence();  // acquire: invalidate L1 before consuming others' writes
    }
    __syncthreads();
}

__device__ __forceinline__ float sigmoidf_(float x) {
    return 1.0f / (1.0f + __expf(-x));
}

// ======================= Phase A: gi0 = x @ W_ih0^T + b_ih0 ===========================
// C tile: 64 rows (batch) x 64 cols. Row index in d_g0 is (t*64 + b).
__global__ __launch_bounds__(256) void gru_phaseA(const float* __restrict__ x,
                                                  const float* __restrict__ wih0,
                                                  const float* __restrict__ bih0) {
    __shared__ __align__(16) float As[16][68];
    __shared__ __align__(16) float Bs[16][68];
    const int t    = blockIdx.x;   // 0..511
    const int nblk = blockIdx.y;   // 0..47
    const int tid  = threadIdx.x;
    const int lr = tid >> 2, lq = tid & 3;     // loader: row 0..63, quad 0..3
    const int tx = tid & 15, ty = tid >> 4;    // compute: 4 rows x 4 cols micro-tile

    float acc[4][4];
#pragma unroll
    for (int i = 0; i < 4; i++)
#pragma unroll
        for (int j = 0; j < 4; j++) acc[i][j] = 0.0f;

    const float* xrow = x + ((size_t)lr * SS + t) * CC;            // batch row lr, time t
    const float* wrow = wih0 + (size_t)(nblk * 64 + lr) * CC;

    float4 av = *(const float4*)(xrow + lq * 4);
    float4 bv = *(const float4*)(wrow + lq * 4);

    for (int k0 = 0; k0 < CC; k0 += 16) {
        __syncthreads();
        As[lq*4+0][lr] = av.x; As[lq*4+1][lr] = av.y; As[lq*4+2][lr] = av.z; As[lq*4+3][lr] = av.w;
        Bs[lq*4+0][lr] = bv.x; Bs[lq*4+1][lr] = bv.y; Bs[lq*4+2][lr] = bv.z; Bs[lq*4+3][lr] = bv.w;
        __syncthreads();
        if (k0 + 16 < CC) {  // prefetch next chunk
            av = *(const float4*)(xrow + k0 + 16 + lq * 4);
            bv = *(const float4*)(wrow + k0 + 16 + lq * 4);
        }
#pragma unroll
        for (int kk = 0; kk < 16; kk++) {
            float4 a = *(const float4*)&As[kk][tx * 4];
            float4 b = *(const float4*)&Bs[kk][ty * 4];
            float ar[4] = {a.x, a.y, a.z, a.w};
            float br[4] = {b.x, b.y, b.z, b.w};
#pragma unroll
            for (int i = 0; i < 4; i++)
#pragma unroll
                for (int j = 0; j < 4; j++) acc[i][j] += ar[i] * br[j];
        }
    }

    const int colb = nblk * 64 + ty * 4;
    float4 bias4 = *(const float4*)(bih0 + colb);
#pragma unroll
    for (int i = 0; i < 4; i++) {
        size_t m = (size_t)t * 64 + tx * 4 + i;
        float4 o;
        o.x = acc[i][0] + bias4.x;
        o.y = acc[i][1] + bias4.y;
        o.z = acc[i][2] + bias4.z;
        o.w = acc[i][3] + bias4.w;
        *(float4*)(d_g0 + m * G3 + colb) = o;
    }
}

// ======================= Phase B job: one hcol tile (16 cols -> 48 gate cols) =================
// MODE 0: layer0 gh + gates -> h0_new  (ih-part from d_g0)
// MODE 1: layer1 gh + b_hh  -> d_gh1   (raw, packed hc*3+g)
// MODE 2: layer1 gi + gates -> h1_new  (hh-part from d_gh1)
template <int MODE>
__device__ __forceinline__ void gru_job(int t, int c0,
                                        const float* __restrict__ hA,
                                        const float* __restrict__ W,
                                        const float* __restrict__ bias,
                                        const float* __restrict__ hprev,
                                        float* __restrict__ hout,
                                        float (&As)[16][68], float (&Bs)[16][52]) {
    const int tid = threadIdx.x;
    const int lr = tid >> 2, lq = tid & 3;
    const int tx = tid & 15, ty = tid >> 4;   // thread owns rows 4tx..4tx+3, hidden col c0+ty

    float acc[4][3];
#pragma unroll
    for (int i = 0; i < 4; i++) { acc[i][0] = 0.f; acc[i][1] = 0.f; acc[i][2] = 0.f; }

    const float* arow = hA + (size_t)lr * HH;
    const float* wrow = nullptr;
    if (lr < 48) {
        int g  = lr % 3;        // gate (r,z,n)
        int hc = lr / 3;        // local hidden col
        wrow = W + (size_t)(g * HH + c0 + hc) * CC;
    }

    float4 av = *(const float4*)(arow + lq * 4);
    float4 bv = make_float4(0.f, 0.f, 0.f, 0.f);
    if (lr < 48) bv = *(const float4*)(wrow + lq * 4);

    for (int k0 = 0; k0 < CC; k0 += 16) {
        __syncthreads();
        As[lq*4+0][lr] = av.x; As[lq*4+1][lr] = av.y; As[lq*4+2][lr] = av.z; As[lq*4+3][lr] = av.w;
        if (lr < 48) {
            Bs[lq*4+0][lr] = bv.x; Bs[lq*4+1][lr] = bv.y; Bs[lq*4+2][lr] = bv.z; Bs[lq*4+3][lr] = bv.w;
        }
        __syncthreads();
        if (k0 + 16 < CC) {
            av = *(const float4*)(arow + k0 + 16 + lq * 4);
            if (lr < 48) bv = *(const float4*)(wrow + k0 + 16 + lq * 4);
        }
#pragma unroll
        for (int kk = 0; kk < 16; kk++) {
            float4 a = *(const float4*)&As[kk][tx * 4];
            float b0 = Bs[kk][ty * 3 + 0];
            float b1 = Bs[kk][ty * 3 + 1];
            float b2 = Bs[kk][ty * 3 + 2];
            acc[0][0] += a.x * b0; acc[0][1] += a.x * b1; acc[0][2] += a.x * b2;
            acc[1][0] += a.y * b0; acc[1][1] += a.y * b1; acc[1][2] += a.y * b2;
            acc[2][0] += a.z * b0; acc[2][1] += a.z * b1; acc[2][2] += a.z * b2;
            acc[3][0] += a.w * b0; acc[3][1] += a.w * b1; acc[3][2] += a.w * b2;
        }
    }

    const int hc = c0 + ty;
    const float b_r = bias[hc], b_z = bias[HH + hc], b_n = bias[2 * HH + hc];

    if (MODE == 1) {
#pragma unroll
        for (int i = 0; i < 4; i++) {
            int row = tx * 4 + i;
            float* p = d_gh1 + (size_t)row * G3 + hc * 3;
            p[0] = acc[i][0] + b_r;
            p[1] = acc[i][1] + b_z;
            p[2] = acc[i][2] + b_n;
        }
    } else if (MODE == 0) {
#pragma unroll
        for (int i = 0; i < 4; i++) {
            int row = tx * 4 + i;
            const float* g0p = d_g0 + ((size_t)t * BB + row) * G3;
            float i_r = g0p[hc], i_z = g0p[HH + hc], i_n = g0p[2 * HH + hc];
            float h_r = acc[i][0] + b_r;
            float h_z = acc[i][1] + b_z;
            float h_n = acc[i][2] + b_n;
            float r = sigmoidf_(i_r + h_r);
            float z = sigmoidf_(i_z + h_z);
            float n = tanhf(i_n + r * h_n);
            float hp = hprev[(size_t)row * HH + hc];
            hout[(size_t)row * HH + hc] = (1.f - z) * n + z * hp;
        }
    } else {  // MODE 2
#pragma unroll
        for (int i = 0; i < 4; i++) {
            int row = tx * 4 + i;
            const float* p = d_gh1 + (size_t)row * G3 + hc * 3;
            float h_r = p[0], h_z = p[1], h_n = p[2];
            float i_r = acc[i][0] + b_r;
            float i_z = acc[i][1] + b_z;
            float i_n = acc[i][2] + b_n;
            float r = sigmoidf_(i_r + h_r);
            float z = sigmoidf_(i_z + h_z);
            float n = tanhf(i_n + r * h_n);
            float hp = hprev[(size_t)row * HH + hc];
            hout[(size_t)row * HH + hc] = (1.f - z) * n + z * hp;
        }
    }
}

// ======================= Phase B: persistent sequential recurrence =======================
__global__ __launch_bounds__(256) void gru_phaseB(const float* __restrict__ wih,
                                                  const float* __restrict__ whh,
                                                  const float* __restrict__ bih,
                                                  const float* __restrict__ bhh,
                                                  float* __restrict__ out) {
    __shared__ __align__(16) float As[16][68];
    __shared__ __align__(16) float Bs[16][52];
    const int nb = gridDim.x;
    const int tid = threadIdx.x;

    // zero-init h states (buffer 0)
    for (int i = blockIdx.x * blockDim.x + tid; i < BB * HH; i += nb * blockDim.x) {
        d_h0[0][i] = 0.f;
        d_h1[0][i] = 0.f;
    }
    grid_sync(nb);

    for (int t = 0; t < SS; t++) {
        const int cur = t & 1, nxt = cur ^ 1;

        // Stage 1: layer0 full update (jobs 0..63) + layer1 recurrent gemm (jobs 64..127)
        for (int job = blockIdx.x; job < 128; job += nb) {
            const int c0 = (job & 63) * 16;
            if (job < 64)
                gru_job<0>(t, c0, d_h0[cur], whh, bhh, d_h0[cur], d_h0[nxt], As, Bs);
            else
                gru_job<1>(t, c0, d_h1[cur], whh + (size_t)G3 * HH, bhh + G3,
                           nullptr, nullptr, As, Bs);
        }
        grid_sync(nb);

        // Stage 2: layer1 input gemm (from fresh h0) + gates
        for (int job = blockIdx.x; job < 64; job += nb) {
            const int c0 = job * 16;
            gru_job<2>(t, c0, d_h0[nxt], wih + (size_t)G3 * CC, bih + G3,
                       d_h1[cur], d_h1[nxt], As, Bs);
        }
        grid_sync(nb);
    }

    // final hidden of layer 1 lives in buffer (SS & 1) ^ 1 ... after t=511: written to buffer 0
    for (int i = blockIdx.x * blockDim.x + tid; i < BB * HH; i += nb * blockDim.x)
        out[i] = d_h1[0][i];
}

// ================================= host launcher =================================
extern "C" void kernel_launch(void* const* d_in, const int* in_sizes, int n_in,
                              void* d_out, int out_size) {
    const float* x   = (const float*)d_in[0];  // [64, 512, 1024]
    const float* wih = (const float*)d_in[1];  // [2, 3072, 1024]
    const float* whh = (const float*)d_in[2];  // [2, 3072, 1024]
    const float* bih = (const float*)d_in[3];  // [2, 3072]
    const float* bhh = (const float*)d_in[4];  // [2, 3072]
    float* out = (float*)d_out;                // [64, 1024]

    int nsm = 0;
    cudaDeviceGetAttribute(&nsm, cudaDevAttrMultiProcessorCount, 0);
    if (nsm <= 0) nsm = 132;  // conservative fallback

    dim3 ga(SS, G3 / 64);
    gru_phaseA<<<ga, 256>>>(x, wih, bih);
    gru_phaseB<<<nsm, 256>>>(wih, whh, bih, bhh, out);
}

// round 3
// speedup vs baseline: 1.0074x; 1.0074x over previous
#include <cuda_runtime.h>
#include <math.h>

#define BB 64
#define SS 512
#define CC 1024
#define HH 1024
#define G3 3072   // 3*H

// ---------------- scratch (static device globals; no runtime allocation) ----------------
__device__ float d_g0[(size_t)SS * BB * G3];   // precomputed layer-0 input projections (+b_ih0)
__device__ float d_h0[2][BB * HH];             // double-buffered layer-0 hidden
__device__ float d_h1[2][BB * HH];             // double-buffered layer-1 hidden
__device__ float d_gh1[BB * G3];               // layer-1 recurrent gates buffer, packed (hc*3+g)
__device__ unsigned int d_bar_arrive;
__device__ unsigned int d_bar_gen;

// ---------------- grid-wide barrier (sense-reversing via generation counter) ----------------
__device__ __forceinline__ void grid_sync(int nblocks) {
    __syncthreads();
    if (threadIdx.x == 0) {
        __threadfence();  // publish our writes (also CCTL.IVALL -> L1 invalidate on this arch)
        unsigned int gen = *((volatile unsigned int*)&d_bar_gen);
        if (atomicAdd(&d_bar_arrive, 1u) == (unsigned int)(nblocks - 1)) {
            atomicExch(&d_bar_arrive, 0u);
            __threadfence();
            atomicExch(&d_bar_gen, gen + 1u);
        } else {
            while (*((volatile unsigned int*)&d_bar_gen) == gen) { __nanosleep(64); }
        }
        __threadfence();  // acquire: invalidate L1 before consuming others' writes
    }
    __syncthreads();
}

__device__ __forceinline__ float sigmoidf_(float x) {
    return 1.0f / (1.0f + __expf(-x));
}

// ======================= Phase A: gi0 = x @ W_ih0^T + b_ih0 ===========================
// C tile: 64 rows (batch) x 64 cols. Row index in d_g0 is (t*64 + b).
__global__ __launch_bounds__(256) void gru_phaseA(const float* __restrict__ x,
                                                  const float* __restrict__ wih0,
                                                  const float* __restrict__ bih0) {
    __shared__ __align__(16) float As[16][68];
    __shared__ __align__(16) float Bs[16][68];
    const int t    = blockIdx.x;   // 0..511
    const int nblk = blockIdx.y;   // 0..47
    const int tid  = threadIdx.x;
    const int lr = tid >> 2, lq = tid & 3;     // loader: row 0..63, quad 0..3
    const int tx = tid & 15, ty = tid >> 4;    // compute: 4 rows x 4 cols micro-tile

    float acc[4][4];
#pragma unroll
    for (int i = 0; i < 4; i++)
#pragma unroll
        for (int j = 0; j < 4; j++) acc[i][j] = 0.0f;

    const float* xrow = x + ((size_t)lr * SS + t) * CC;            // batch row lr, time t
    const float* wrow = wih0 + (size_t)(nblk * 64 + lr) * CC;

    float4 av = *(const float4*)(xrow + lq * 4);
    float4 bv = *(const float4*)(wrow + lq * 4);

    for (int k0 = 0; k0 < CC; k0 += 16) {
        __syncthreads();
        As[lq*4+0][lr] = av.x; As[lq*4+1][lr] = av.y; As[lq*4+2][lr] = av.z; As[lq*4+3][lr] = av.w;
        Bs[lq*4+0][lr] = bv.x; Bs[lq*4+1][lr] = bv.y; Bs[lq*4+2][lr] = bv.z; Bs[lq*4+3][lr] = bv.w;
        __syncthreads();
        if (k0 + 16 < CC) {  // prefetch next chunk
            av = *(const float4*)(xrow + k0 + 16 + lq * 4);
            bv = *(const float4*)(wrow + k0 + 16 + lq * 4);
        }
#pragma unroll
        for (int kk = 0; kk < 16; kk++) {
            float4 a = *(const float4*)&As[kk][tx * 4];
            float4 b = *(const float4*)&Bs[kk][ty * 4];
            float ar[4] = {a.x, a.y, a.z, a.w};
            float br[4] = {b.x, b.y, b.z, b.w};
#pragma unroll
            for (int i = 0; i < 4; i++)
#pragma unroll
                for (int j = 0; j < 4; j++) acc[i][j] += ar[i] * br[j];
        }
    }

    const int colb = nblk * 64 + ty * 4;
    float4 bias4 = *(const float4*)(bih0 + colb);
#pragma unroll
    for (int i = 0; i < 4; i++) {
        size_t m = (size_t)t * 64 + tx * 4 + i;
        float4 o;
        o.x = acc[i][0] + bias4.x;
        o.y = acc[i][1] + bias4.y;
        o.z = acc[i][2] + bias4.z;
        o.w = acc[i][3] + bias4.w;
        *(float4*)(d_g0 + m * G3 + colb) = o;
    }
}

// ======================= Phase B job: one hcol tile (16 cols -> 48 gate cols) =================
// MODE 0: layer0 gh + gates -> h0_new  (ih-part from d_g0)
// MODE 1: layer1 gh + b_hh  -> d_gh1   (raw, packed hc*3+g)
// MODE 2: layer1 gi + gates -> h1_new  (hh-part from d_gh1)
template <int MODE>
__device__ __forceinline__ void gru_job(int t, int c0,
                                        const float* __restrict__ hA,
                                        const float* __restrict__ W,
                                        const float* __restrict__ bias,
                                        const float* __restrict__ hprev,
                                        float* __restrict__ hout,
                                        float (&As)[16][68], float (&Bs)[16][52]) {
    const int tid = threadIdx.x;
    const int lr = tid >> 2, lq = tid & 3;
    const int tx = tid & 15, ty = tid >> 4;   // thread owns rows 4tx..4tx+3, hidden col c0+ty

    float acc[4][3];
#pragma unroll
    for (int i = 0; i < 4; i++) { acc[i][0] = 0.f; acc[i][1] = 0.f; acc[i][2] = 0.f; }

    const float* arow = hA + (size_t)lr * HH;
    const float* wrow = nullptr;
    if (lr < 48) {
        int g  = lr % 3;        // gate (r,z,n)
        int hc = lr / 3;        // local hidden col
        wrow = W + (size_t)(g * HH + c0 + hc) * CC;
    }

    float4 av = *(const float4*)(arow + lq * 4);
    float4 bv = make_float4(0.f, 0.f, 0.f, 0.f);
    if (lr < 48) bv = *(const float4*)(wrow + lq * 4);

    for (int k0 = 0; k0 < CC; k0 += 16) {
        __syncthreads();
        As[lq*4+0][lr] = av.x; As[lq*4+1][lr] = av.y; As[lq*4+2][lr] = av.z; As[lq*4+3][lr] = av.w;
        if (lr < 48) {
            Bs[lq*4+0][lr] = bv.x; Bs[lq*4+1][lr] = bv.y; Bs[lq*4+2][lr] = bv.z; Bs[lq*4+3][lr] = bv.w;
        }
        __syncthreads();
        if (k0 + 16 < CC) {
            av = *(const float4*)(arow + k0 + 16 + lq * 4);
            if (lr < 48) bv = *(const float4*)(wrow + k0 + 16 + lq * 4);
        }
#pragma unroll
        for (int kk = 0; kk < 16; kk++) {
            float4 a = *(const float4*)&As[kk][tx * 4];
            float b0 = Bs[kk][ty * 3 + 0];
            float b1 = Bs[kk][ty * 3 + 1];
            float b2 = Bs[kk][ty * 3 + 2];
            acc[0][0] += a.x * b0; acc[0][1] += a.x * b1; acc[0][2] += a.x * b2;
            acc[1][0] += a.y * b0; acc[1][1] += a.y * b1; acc[1][2] += a.y * b2;
            acc[2][0] += a.z * b0; acc[2][1] += a.z * b1; acc[2][2] += a.z * b2;
            acc[3][0] += a.w * b0; acc[3][1] += a.w * b1; acc[3][2] += a.w * b2;
        }
    }

    const int hc = c0 + ty;
    const float b_r = bias[hc], b_z = bias[HH + hc], b_n = bias[2 * HH + hc];

    if (MODE == 1) {
#pragma unroll
        for (int i = 0; i < 4; i++) {
            int row = tx * 4 + i;
            float* p = d_gh1 + (size_t)row * G3 + hc * 3;
            p[0] = acc[i][0] + b_r;
            p[1] = acc[i][1] + b_z;
            p[2] = acc[i][2] + b_n;
        }
    } else if (MODE == 0) {
#pragma unroll
        for (int i = 0; i < 4; i++) {
            int row = tx * 4 + i;
            const float* g0p = d_g0 + ((size_t)t * BB + row) * G3;
            float i_r = g0p[hc], i_z = g0p[HH + hc], i_n = g0p[2 * HH + hc];
            float h_r = acc[i][0] + b_r;
            float h_z = acc[i][1] + b_z;
            float h_n = acc[i][2] + b_n;
            float r = sigmoidf_(i_r + h_r);
            float z = sigmoidf_(i_z + h_z);
            float n = tanhf(i_n + r * h_n);
            float hp = hprev[(size_t)row * HH + hc];
            hout[(size_t)row * HH + hc] = (1.f - z) * n + z * hp;
        }
    } else {  // MODE 2
#pragma unroll
        for (int i = 0; i < 4; i++) {
            int row = tx * 4 + i;
            const float* p = d_gh1 + (size_t)row * G3 + hc * 3;
            float h_r = p[0], h_z = p[1], h_n = p[2];
            float i_r = acc[i][0] + b_r;
            float i_z = acc[i][1] + b_z;
            float i_n = acc[i][2] + b_n;
            float r = sigmoidf_(i_r + h_r);
            float z = sigmoidf_(i_z + h_z);
            float n = tanhf(i_n + r * h_n);
            float hp = hprev[(size_t)row * HH + hc];
            hout[(size_t)row * HH + hc] = (1.f - z) * n + z * hp;
        }
    }
}

// ======================= Phase B: persistent sequential recurrence =======================
__global__ __launch_bounds__(256) void gru_phaseB(const float* __restrict__ wih,
                                                  const float* __restrict__ whh,
                                                  const float* __restrict__ bih,
                                                  const float* __restrict__ bhh,
                                                  float* __restrict__ out) {
    __shared__ __align__(16) float As[16][68];
    __shared__ __align__(16) float Bs[16][52];
    const int nb = gridDim.x;
    const int tid = threadIdx.x;

    // zero-init h states (buffer 0)
    for (int i = blockIdx.x * blockDim.x + tid; i < BB * HH; i += nb * blockDim.x) {
        d_h0[0][i] = 0.f;
        d_h1[0][i] = 0.f;
    }
    grid_sync(nb);

    for (int t = 0; t < SS; t++) {
        const int cur = t & 1, nxt = cur ^ 1;

        // Stage 1: layer0 full update (jobs 0..63) + layer1 recurrent gemm (jobs 64..127)
        for (int job = blockIdx.x; job < 128; job += nb) {
            const int c0 = (job & 63) * 16;
            if (job < 64)
                gru_job<0>(t, c0, d_h0[cur], whh, bhh, d_h0[cur], d_h0[nxt], As, Bs);
            else
                gru_job<1>(t, c0, d_h1[cur], whh + (size_t)G3 * HH, bhh + G3,
                           nullptr, nullptr, As, Bs);
        }
        grid_sync(nb);

        // Stage 2: layer1 input gemm (from fresh h0) + gates
        for (int job = blockIdx.x; job < 64; job += nb) {
            const int c0 = job * 16;
            gru_job<2>(t, c0, d_h0[nxt], wih + (size_t)G3 * CC, bih + G3,
                       d_h1[cur], d_h1[nxt], As, Bs);
        }
        grid_sync(nb);
    }

    // final hidden of layer 1 lives in buffer (SS & 1) ^ 1 ... after t=511: written to buffer 0
    for (int i = blockIdx.x * blockDim.x + tid; i < BB * HH; i += nb * blockDim.x)
        out[i] = d_h1[0][i];
}

// ================================= host launcher =================================
extern "C" void kernel_launch(void* const* d_in, const int* in_sizes, int n_in,
                              void* d_out, int out_size) {
    const float* x   = (const float*)d_in[0];  // [64, 512, 1024]
    const float* wih = (const float*)d_in[1];  // [2, 3072, 1024]
    const float* whh = (const float*)d_in[2];  // [2, 3072, 1024]
    const float* bih = (const float*)d_in[3];  // [2, 3072]
    const float* bhh = (const float*)d_in[4];  // [2, 3072]
    float* out = (float*)d_out;                // [64, 1024]

    int nsm = 0;
    cudaDeviceGetAttribute(&nsm, cudaDevAttrMultiProcessorCount, 0);
    if (nsm <= 0) nsm = 132;  // conservative fallback

    dim3 ga(SS, G3 / 64);
    gru_phaseA<<<ga, 256>>>(x, wih, bih);
    gru_phaseB<<<nsm, 256>>>(wih, whh, bih, bhh, out);
}

// round 6
// speedup vs baseline: 3.4209x; 3.3957x over previous
#include <cuda_runtime.h>
#include <cuda_bf16.h>
#include <cstdint>
#include <math.h>

#define BB 64
#define SS 512
#define CC 1024
#define HH 1024
#define G3 3072

// image sizes
#define WTB   196608u    // weight tile: 8 chunks x (BHI 12288 + BLO 12288)
#define AIMG  524288u    // x image per 128-row block: 8 chunks x (AHI 32768 + ALO 32768)
#define HIMG  262144u    // h image per buffer: 8 chunks x (AHI 16384 + ALO 16384)

// ---------------- device globals ----------------
__device__ __align__(16) float   d_g0[(size_t)SS * BB * G3];   // layer-0 gi (+bih0), packed [m][ct*48 + g*16+i]
__device__ __align__(16) float   d_h0f[2][BB * HH];
__device__ __align__(16) float   d_h1f[2][BB * HH];
__device__ __align__(16) float   d_gh1[BB * G3];               // layer-1 gh (+bhh1)
__device__ __align__(128) uint8_t d_wimg[256ull * WTB];        // tiles: 0-63 Wih0, 64-127 Whh0, 128-191 Whh1, 192-255 Wih1
__device__ __align__(128) uint8_t d_ximg[256ull * AIMG];
__device__ __align__(128) uint8_t d_himg0[2][HIMG];
__device__ __align__(128) uint8_t d_himg1[2][HIMG];
__device__ unsigned int d_bar_arrive;
__device__ unsigned int d_bar_gen;

// ---------------- helpers ----------------
__device__ __forceinline__ uint32_t smem_u32(const void* p) {
    uint32_t a;
    asm("{ .reg .u64 t; cvta.to.shared.u64 t, %1; cvt.u32.u64 %0, t; }" : "=r"(a) : "l"(p));
    return a;
}
__device__ __forceinline__ void cp_async16(uint32_t s, const void* g) {
    asm volatile("cp.async.cg.shared.global [%0], [%1], 16;" :: "r"(s), "l"(g));
}
#define CP_COMMIT() asm volatile("cp.async.commit_group;" ::: "memory")
#define CP_WAIT1()  asm volatile("cp.async.wait_group 1;" ::: "memory")
#define CP_WAIT0()  asm volatile("cp.async.wait_group 0;" ::: "memory")

__device__ __forceinline__ void mma16816(float (&d)[4], const uint32_t* a, const uint32_t* b) {
    asm volatile("mma.sync.aligned.m16n8k16.row.col.f32.bf16.bf16.f32 "
        "{%0,%1,%2,%3}, {%4,%5,%6,%7}, {%8,%9}, {%0,%1,%2,%3};"
        : "+f"(d[0]), "+f"(d[1]), "+f"(d[2]), "+f"(d[3])
        : "r"(a[0]), "r"(a[1]), "r"(a[2]), "r"(a[3]), "r"(b[0]), "r"(b[1]));
}

__device__ __forceinline__ void cvt2(float a, float b, uint32_t& hi, uint32_t& lo) {
    __nv_bfloat162 h = __floats2bfloat162_rn(a, b);
    float2 f = __bfloat1622float2(h);
    __nv_bfloat162 l = __floats2bfloat162_rn(a - f.x, b - f.y);
    hi = *(uint32_t*)&h;
    lo = *(uint32_t*)&l;
}
__device__ __forceinline__ float sigm(float x) { return 1.0f / (1.0f + __expf(-x)); }

// ---------------- grid barrier (validated in R1/R3) ----------------
__device__ __forceinline__ void grid_sync(int nblocks) {
    __syncthreads();
    if (threadIdx.x == 0) {
        __threadfence();
        unsigned int gen = *((volatile unsigned int*)&d_bar_gen);
        if (atomicAdd(&d_bar_arrive, 1u) == (unsigned int)(nblocks - 1)) {
            atomicExch(&d_bar_arrive, 0u);
            __threadfence();
            atomicExch(&d_bar_gen, gen + 1u);
        } else {
            while (*((volatile unsigned int*)&d_bar_gen) == gen) { __nanosleep(64); }
        }
        __threadfence();
    }
    __syncthreads();
}

// ---------------- fragment compute: 6 n-tiles x 8 k-steps x 3 passes ----------------
template <bool M128>
__device__ __forceinline__ void compute_chunk(char* buf, float (&acc)[6][4], int w, int lane) {
    constexpr int APLANE = M128 ? 32768 : 16384;
    char* aph = buf + w * 4096 + lane * 16;
    char* apl = aph + APLANE;
    char* bp  = buf + 2 * APLANE + lane * 8;
#pragma unroll
    for (int ks = 0; ks < 8; ks++) {
        uint32_t ah[4], al[4];
        *(uint4*)ah = *(const uint4*)(aph + ks * 512);
        *(uint4*)al = *(const uint4*)(apl + ks * 512);
#pragma unroll
        for (int nt = 0; nt < 6; nt++) {
            uint32_t bh[2], bl[2];
            *(uint2*)bh = *(const uint2*)(bp + nt * 2048 + ks * 256);
            *(uint2*)bl = *(const uint2*)(bp + 12288 + nt * 2048 + ks * 256);
            mma16816(acc[nt], ah, bh);
            mma16816(acc[nt], ah, bl);
            mma16816(acc[nt], al, bh);
        }
    }
}

// ---------------- one GEMM job with fused epilogue ----------------
// MODE 0: layer0 update (acc=gh, gsrc=gi)   MODE 1: layer1 gh raw (+bhh1) -> outg
// MODE 2: layer1 update (acc=gi, gsrc=gh)   MODE 3: phase A (M=128) -> outg (+bih0)
template <int MODE>
__device__ void run_job(char* smem, uint32_t sb,
                        const uint8_t* __restrict__ aimg, const uint8_t* __restrict__ wimg,
                        const float* __restrict__ bias, int ct,
                        const float* __restrict__ gsrc, const float* __restrict__ hprevf,
                        float* __restrict__ houtf, uint8_t* __restrict__ himg_out,
                        float* __restrict__ outg) {
    constexpr bool M128 = (MODE == 3);
    constexpr int ABYTES = M128 ? 65536 : 32768;
    constexpr int BUFB = ABYTES + 24576;
    const int tid = threadIdx.x, w = tid >> 5, lane = tid & 31;

    // chunk 0 copy
    for (int i = tid * 16; i < ABYTES; i += 4096) cp_async16(sb + i, aimg + i);
    for (int i = tid * 16; i < 24576; i += 4096) cp_async16(sb + ABYTES + i, wimg + i);
    CP_COMMIT();

    float acc[6][4];
#pragma unroll
    for (int n = 0; n < 6; n++)
#pragma unroll
        for (int q = 0; q < 4; q++) acc[n][q] = 0.f;

    for (int c = 0; c < 8; c++) {
        if (c < 7) {
            const uint32_t db = sb + ((c + 1) & 1) * BUFB;
            const uint8_t* as = aimg + (size_t)(c + 1) * ABYTES;
            for (int i = tid * 16; i < ABYTES; i += 4096) cp_async16(db + i, as + i);
            const uint8_t* bs = wimg + (size_t)(c + 1) * 24576;
            for (int i = tid * 16; i < 24576; i += 4096) cp_async16(db + ABYTES + i, bs + i);
            CP_COMMIT();
            CP_WAIT1();
        } else {
            CP_WAIT0();
        }
        __syncthreads();
        if (M128 || w < 4) compute_chunk<M128>(smem + (c & 1) * BUFB, acc, w, lane);
        __syncthreads();
    }

    if (M128 || w < 4) {
        const int r0 = w * 16 + (lane >> 2), r1 = r0 + 8;
        const int cb = ct * 48, hb16 = ct * 16;

        if (MODE == 1 || MODE == 3) {
#pragma unroll
            for (int nt = 0; nt < 6; nt++) {
                const int g = nt >> 1, i = (nt & 1) * 8 + (lane & 3) * 2;
                float2 bs = *(const float2*)(bias + g * HH + hb16 + i);
                *(float2*)(outg + (size_t)r0 * G3 + cb + nt * 8 + (lane & 3) * 2) =
                    make_float2(acc[nt][0] + bs.x, acc[nt][1] + bs.y);
                *(float2*)(outg + (size_t)r1 * G3 + cb + nt * 8 + (lane & 3) * 2) =
                    make_float2(acc[nt][2] + bs.x, acc[nt][3] + bs.y);
            }
        } else {
            const uint32_t chb = (uint32_t)(ct >> 3) * 32768u + (uint32_t)(ct & 7) * 512u +
                                 (uint32_t)w * 4096u + (uint32_t)((lane >> 2) * 4 + (lane & 3)) * 16u;
#pragma unroll
            for (int ntb = 0; ntb < 2; ntb++) {
                const int i = ntb * 8 + (lane & 3) * 2;
                float2 br = *(const float2*)(bias + hb16 + i);
                float2 bz = *(const float2*)(bias + HH + hb16 + i);
                float2 bn = *(const float2*)(bias + 2 * HH + hb16 + i);
#pragma unroll
                for (int rs = 0; rs < 2; rs++) {
                    const int row = rs ? r1 : r0;
                    const int di = rs * 2;
                    float a_r0 = acc[ntb][di] + br.x,     a_r1 = acc[ntb][di + 1] + br.y;
                    float a_z0 = acc[2 + ntb][di] + bz.x, a_z1 = acc[2 + ntb][di + 1] + bz.y;
                    float a_n0 = acc[4 + ntb][di] + bn.x, a_n1 = acc[4 + ntb][di + 1] + bn.y;
                    const float* gp = gsrc + (size_t)row * G3 + cb;
                    float2 gr = *(const float2*)(gp + i);
                    float2 gz = *(const float2*)(gp + 16 + i);
                    float2 gn = *(const float2*)(gp + 32 + i);
                    float ir0, iz0, in0, hr0, hz0, hn0, ir1, iz1, in1, hr1, hz1, hn1;
                    if (MODE == 0) {
                        ir0 = gr.x; iz0 = gz.x; in0 = gn.x; hr0 = a_r0; hz0 = a_z0; hn0 = a_n0;
                        ir1 = gr.y; iz1 = gz.y; in1 = gn.y; hr1 = a_r1; hz1 = a_z1; hn1 = a_n1;
                    } else {
                        hr0 = gr.x; hz0 = gz.x; hn0 = gn.x; ir0 = a_r0; iz0 = a_z0; in0 = a_n0;
                        hr1 = gr.y; hz1 = gz.y; hn1 = gn.y; ir1 = a_r1; iz1 = a_z1; in1 = a_n1;
                    }
                    float rr0 = sigm(ir0 + hr0), zz0 = sigm(iz0 + hz0);
                    float rr1 = sigm(ir1 + hr1), zz1 = sigm(iz1 + hz1);
                    float nn0 = tanhf(in0 + rr0 * hn0);
                    float nn1 = tanhf(in1 + rr1 * hn1);
                    float2 hp = *(const float2*)(hprevf + (size_t)row * HH + hb16 + i);
                    float h0v = (1.f - zz0) * nn0 + zz0 * hp.x;
                    float h1v = (1.f - zz1) * nn1 + zz1 * hp.y;
                    *(float2*)(houtf + (size_t)row * HH + hb16 + i) = make_float2(h0v, h1v);
                    uint32_t hb, lb;
                    cvt2(h0v, h1v, hb, lb);
                    const uint32_t ea = chb + (uint32_t)(rs + 2 * ntb) * 4u;
                    *(uint32_t*)(himg_out + ea) = hb;
                    *(uint32_t*)(himg_out + 16384 + ea) = lb;
                }
            }
        }
    }
    __syncthreads();   // hardened: uniform re-convergence before any subsequent job touches smem
}

// ---------------- prep: weights -> fragment-linear bf16 hi/lo images ----------------
__global__ __launch_bounds__(256) void prep_w(const float* __restrict__ wih, const float* __restrict__ whh) {
    const int tile = blockIdx.x;
    const float* W;
    if (tile < 64)       W = wih;
    else if (tile < 128) W = whh;
    else if (tile < 192) W = whh + (size_t)G3 * HH;
    else                 W = wih + (size_t)G3 * CC;
    const int ct = tile & 63;
    uint8_t* img = d_wimg + (size_t)tile * WTB;
    for (int idx = threadIdx.x; idx < 48 * 512; idx += 256) {
        const int j = idx >> 9, kp = idx & 511, k = kp * 2;
        const int g = j >> 4, i2 = j & 15;
        float2 v = *(const float2*)(W + (size_t)(g * HH + ct * 16 + i2) * CC + k);
        uint32_t hb, lb;
        cvt2(v.x, v.y, hb, lb);
        const int chunk = k >> 7, ks = (k >> 4) & 7, kk = k & 15;
        const int nt = j >> 3, n8 = j & 7;
        const uint32_t off = (uint32_t)chunk * 24576u + (uint32_t)nt * 2048u + (uint32_t)ks * 256u +
                             (uint32_t)(n8 * 4 + ((kk & 7) >> 1)) * 8u + (uint32_t)(kk >> 3) * 4u;
        *(uint32_t*)(img + off) = hb;
        *(uint32_t*)(img + off + 12288) = lb;
    }
}

// ---------------- prep: x -> fragment-linear A images ----------------
__global__ __launch_bounds__(256) void prep_x(const float* __restrict__ x) {
    const int mb = blockIdx.x >> 3, c = blockIdx.x & 7;
    uint8_t* img = d_ximg + (size_t)mb * AIMG + (size_t)c * 65536;
    for (int idx = threadIdx.x; idx < 128 * 64; idx += 256) {
        const int row = idx >> 6, kp = idx & 63, k = kp * 2;
        const int m = mb * 128 + row, t = m >> 6, b = m & 63;
        float2 v = *(const float2*)(x + ((size_t)b * SS + t) * CC + c * 128 + k);
        uint32_t hb, lb;
        cvt2(v.x, v.y, hb, lb);
        const int r16 = row >> 4, ks = k >> 4, kk = k & 15;
        const uint32_t off = (uint32_t)r16 * 4096u + (uint32_t)ks * 512u +
                             (uint32_t)((row & 7) * 4 + ((kk & 7) >> 1)) * 16u +
                             (uint32_t)(((row >> 3) & 1) + 2 * (kk >> 3)) * 4u;
        *(uint32_t*)(img + off) = hb;
        *(uint32_t*)(img + off + 32768) = lb;
    }
}

// ---------------- phase A: gi0 = x @ Wih0^T + bih0 ----------------
__global__ __launch_bounds__(256, 1) void gru_phaseA(const float* __restrict__ bih) {
    extern __shared__ char smem[];
    uint32_t sb = smem_u32(smem);
    const int ct = blockIdx.x, mb = blockIdx.y;
    run_job<3>(smem, sb, d_ximg + (size_t)mb * AIMG, d_wimg + (size_t)ct * WTB,
               bih, ct, nullptr, nullptr, nullptr, nullptr,
               d_g0 + (size_t)mb * 128 * G3);
}

// ---------------- phase B: persistent recurrence ----------------
__global__ __launch_bounds__(256, 1) void gru_phaseB(const float* __restrict__ bih,
                                                     const float* __restrict__ bhh,
                                                     float* __restrict__ out) {
    extern __shared__ char smem[];
    uint32_t sb = smem_u32(smem);
    const int nb = gridDim.x, tid = threadIdx.x;
    const int gidx = blockIdx.x * 256 + tid, gs = nb * 256;

    for (int i = gidx; i < BB * HH; i += gs) { d_h0f[0][i] = 0.f; d_h1f[0][i] = 0.f; }
    for (int i = gidx; i < (int)(HIMG / 4); i += gs) {
        ((uint32_t*)d_himg0[0])[i] = 0u;
        ((uint32_t*)d_himg1[0])[i] = 0u;
    }
    grid_sync(nb);

    for (int t = 0; t < SS; t++) {
        const int cur = t & 1, nxt = cur ^ 1;
        for (int job = blockIdx.x; job < 128; job += nb) {
            const int ct = job & 63;
            if (job < 64)
                run_job<0>(smem, sb, d_himg0[cur], d_wimg + (size_t)(64 + ct) * WTB,
                           bhh, ct, d_g0 + (size_t)t * BB * G3, d_h0f[cur], d_h0f[nxt],
                           d_himg0[nxt], nullptr);
            else
                run_job<1>(smem, sb, d_himg1[cur], d_wimg + (size_t)(128 + ct) * WTB,
                           bhh + G3, ct, nullptr, nullptr, nullptr, nullptr, d_gh1);
        }
        grid_sync(nb);
        for (int job = blockIdx.x; job < 64; job += nb)
            run_job<2>(smem, sb, d_himg0[nxt], d_wimg + (size_t)(192 + job) * WTB,
                       bih + G3, job, d_gh1, d_h1f[cur], d_h1f[nxt], d_himg1[nxt], nullptr);
        grid_sync(nb);
    }
    for (int i = gidx; i < BB * HH; i += gs) out[i] = d_h1f[0][i];
}

// ---------------- host launcher ----------------
#define PB_SMEM (2 * (32768 + 24576))   // 114688
#define PA_SMEM (2 * (65536 + 24576))   // 180224

extern "C" void kernel_launch(void* const* d_in, const int* in_sizes, int n_in,
                              void* d_out, int out_size) {
    const float* x   = (const float*)d_in[0];
    const float* wih = (const float*)d_in[1];
    const float* whh = (const float*)d_in[2];
    const float* bih = (const float*)d_in[3];
    const float* bhh = (const float*)d_in[4];
    float* out = (float*)d_out;

    cudaFuncSetAttribute(gru_phaseA, cudaFuncAttributeMaxDynamicSharedMemorySize, PA_SMEM);
    cudaFuncSetAttribute(gru_phaseB, cudaFuncAttributeMaxDynamicSharedMemorySize, PB_SMEM);

    int nsm = 0;
    cudaDeviceGetAttribute(&nsm, cudaDevAttrMultiProcessorCount, 0);
    if (nsm <= 0) nsm = 148;

    prep_w<<<256, 256>>>(wih, whh);
    prep_x<<<2048, 256>>>(x);
    gru_phaseA<<<dim3(64, 256), 256, PA_SMEM>>>(bih);
    gru_phaseB<<<nsm, 256, PB_SMEM>>>(bih, bhh, out);
}